// round 16
// baseline (speedup 1.0000x reference)
#include <cuda_runtime.h>
#include <cuda_fp16.h>
#include <math.h>

#define BB 2
#define HH 16
#define NN 2048
#define DD 64
#define BH (BB*HH)
#define SCALE 0.03125f   // 1/(sqrt(16)*sqrt(64))

// ---------------- scratch (static device globals; no allocation) ----------------
__device__ __half g_qh[(size_t)BH*NN*DD];      // head-mixed q, fp16 [b,e,n,d]
__device__ __half g_kh[(size_t)BH*NN*DD];      // head-mixed k, fp16 [b,e,n,d]
__device__ __half g_vh[(size_t)BH*NN*DD];      // v, fp16 [b,h,n,d]
__device__ __half g_S [(size_t)BH*NN*NN];      // unnormalized exp(s - c), fp16 (256MB)
__device__ float  g_rsum[(size_t)BH*NN];       // softmax row sums
__device__ float  g_psum[(size_t)BH*NN*16];    // per-(row, j-tile) partial sums
__device__ float  g_qnorm[(size_t)BH*NN];      // ||q_mixed_i|| (of fp16 values)
__device__ float  g_kmax[BH];                  // max_j ||k_mixed_j|| per (b,h)
// g_kmax: zero-initialized at load; atomicMax over identical deterministic
// inputs is idempotent -> no per-launch reset needed (graph-capture safe).

// ---------------- helpers ----------------
__device__ __forceinline__ unsigned h2u(float a, float b) {
    __half2 h = __floats2half2_rn(a, b);
    return *(unsigned*)&h;
}
__device__ __forceinline__ float4 u2f4(uint2 u) {
    float2 f0 = __half22float2(*(__half2*)&u.x);
    float2 f1 = __half22float2(*(__half2*)&u.y);
    return make_float4(f0.x, f0.y, f1.x, f1.y);
}
__device__ __forceinline__ unsigned sm_addr(const void* p) {
    return (unsigned)__cvta_generic_to_shared(p);
}
__device__ __forceinline__ void ldsm_x4(unsigned* r, unsigned a) {
    asm volatile("ldmatrix.sync.aligned.m8n8.x4.shared.b16 {%0,%1,%2,%3}, [%4];\n"
        : "=r"(r[0]), "=r"(r[1]), "=r"(r[2]), "=r"(r[3]) : "r"(a));
}
__device__ __forceinline__ void ldsm_x2(unsigned* r, unsigned a) {
    asm volatile("ldmatrix.sync.aligned.m8n8.x2.shared.b16 {%0,%1}, [%2];\n"
        : "=r"(r[0]), "=r"(r[1]) : "r"(a));
}
__device__ __forceinline__ void ldsm_x2t(unsigned* r, unsigned a) {
    asm volatile("ldmatrix.sync.aligned.m8n8.x2.trans.shared.b16 {%0,%1}, [%2];\n"
        : "=r"(r[0]), "=r"(r[1]) : "r"(a));
}
__device__ __forceinline__ void mma16816(float* c, const unsigned* a, const unsigned* b) {
    asm volatile(
        "mma.sync.aligned.m16n8k16.row.col.f32.f16.f16.f32 "
        "{%0,%1,%2,%3}, {%4,%5,%6,%7}, {%8,%9}, {%0,%1,%2,%3};\n"
        : "+f"(c[0]), "+f"(c[1]), "+f"(c[2]), "+f"(c[3])
        : "r"(a[0]), "r"(a[1]), "r"(a[2]), "r"(a[3]), "r"(b[0]), "r"(b[1]));
}
__device__ __forceinline__ void cp16(unsigned s, const void* g) {
    asm volatile("cp.async.cg.shared.global [%0], [%1], 16;\n" :: "r"(s), "l"(g));
}
__device__ __forceinline__ void cp_commit() {
    asm volatile("cp.async.commit_group;\n");
}

// ---- K1: fused prep: head-mix q,k (fp16 out) + v->fp16 + q-norms + k-max ----
// block = 256 threads = 16 rows x 16 d-quads; grid = (NN/16, BB)
__global__ void __launch_bounds__(256) k_prep(const float* __restrict__ q,
                                              const float* __restrict__ k,
                                              const float* __restrict__ v,
                                              const float* __restrict__ Wpre)
{
    __shared__ float Ws[HH][HH];
    __shared__ float snorm[HH][16];

    int tid = threadIdx.x;
    Ws[tid >> 4][tid & 15] = Wpre[tid];
    __syncthreads();

    int b  = blockIdx.y;
    int n0 = blockIdx.x * 16;
    int r  = tid >> 4;               // row 0..15
    int dq = tid & 15;               // d-quad 0..15
    int n  = n0 + r;
    size_t base = ((size_t)b * HH * NN + n) * DD + dq * 4;   // + f*NN*DD per head
    const size_t hs = (size_t)NN * DD;

    float acc4[HH][4];
    float sq[HH];

    // ----- q: mix, store fp16, norm of fp16 values -----
#pragma unroll
    for (int e = 0; e < HH; e++) { acc4[e][0] = acc4[e][1] = acc4[e][2] = acc4[e][3] = 0.f; }
#pragma unroll
    for (int f = 0; f < HH; f++) {
        float4 x = *(const float4*)&q[base + f * hs];
#pragma unroll
        for (int e = 0; e < HH; e++) {
            float w = Ws[e][f];
            acc4[e][0] += w * x.x; acc4[e][1] += w * x.y;
            acc4[e][2] += w * x.z; acc4[e][3] += w * x.w;
        }
    }
#pragma unroll
    for (int e = 0; e < HH; e++) {
        uint2 hv = make_uint2(h2u(acc4[e][0], acc4[e][1]), h2u(acc4[e][2], acc4[e][3]));
        *(uint2*)&g_qh[base + e * hs] = hv;
        float4 fb = u2f4(hv);                       // fp16-rounded values
        sq[e] = fb.x * fb.x + fb.y * fb.y + fb.z * fb.z + fb.w * fb.w;
    }
#pragma unroll
    for (int e = 0; e < HH; e++) {
        float s = sq[e];
        s += __shfl_xor_sync(0xffffffff, s, 1);
        s += __shfl_xor_sync(0xffffffff, s, 2);
        s += __shfl_xor_sync(0xffffffff, s, 4);
        s += __shfl_xor_sync(0xffffffff, s, 8);
        if (dq == 0) snorm[e][r] = s;
    }
    __syncthreads();
    g_qnorm[(size_t)(b * HH + (tid >> 4)) * NN + n0 + (tid & 15)] =
        sqrtf(snorm[tid >> 4][tid & 15]);
    __syncthreads();                                 // before snorm reuse

    // ----- k: mix, store fp16, per-head max norm -----
#pragma unroll
    for (int e = 0; e < HH; e++) { acc4[e][0] = acc4[e][1] = acc4[e][2] = acc4[e][3] = 0.f; }
#pragma unroll
    for (int f = 0; f < HH; f++) {
        float4 x = *(const float4*)&k[base + f * hs];
#pragma unroll
        for (int e = 0; e < HH; e++) {
            float w = Ws[e][f];
            acc4[e][0] += w * x.x; acc4[e][1] += w * x.y;
            acc4[e][2] += w * x.z; acc4[e][3] += w * x.w;
        }
    }
#pragma unroll
    for (int e = 0; e < HH; e++) {
        uint2 hv = make_uint2(h2u(acc4[e][0], acc4[e][1]), h2u(acc4[e][2], acc4[e][3]));
        *(uint2*)&g_kh[base + e * hs] = hv;
        float4 fb = u2f4(hv);
        sq[e] = fb.x * fb.x + fb.y * fb.y + fb.z * fb.z + fb.w * fb.w;
    }
#pragma unroll
    for (int e = 0; e < HH; e++) {
        float s = sq[e];
        s += __shfl_xor_sync(0xffffffff, s, 1);
        s += __shfl_xor_sync(0xffffffff, s, 2);
        s += __shfl_xor_sync(0xffffffff, s, 4);
        s += __shfl_xor_sync(0xffffffff, s, 8);
        if (dq == 0) snorm[e][r] = s;
    }
    __syncthreads();
    {
        float s2 = snorm[tid >> 4][tid & 15];        // (e = tid>>4, row = tid&15)
        s2 = fmaxf(s2, __shfl_xor_sync(0xffffffff, s2, 1));
        s2 = fmaxf(s2, __shfl_xor_sync(0xffffffff, s2, 2));
        s2 = fmaxf(s2, __shfl_xor_sync(0xffffffff, s2, 4));
        s2 = fmaxf(s2, __shfl_xor_sync(0xffffffff, s2, 8));
        if ((tid & 15) == 0)
            atomicMax((int*)&g_kmax[b * HH + (tid >> 4)], __float_as_int(sqrtf(s2)));
    }

    // ----- v -> fp16 (no mixing) -----
#pragma unroll
    for (int f = 0; f < HH; f++) {
        float4 x = *(const float4*)&v[base + f * hs];
        *(uint2*)&g_vh[base + f * hs] = make_uint2(h2u(x.x, x.y), h2u(x.z, x.w));
    }
}

// ---- K2: lower-tri 128x128x64 tensor-core GEMM + fused exp(s-c) + partial sums,
//      coalesced S store via smem staging (reuses Q/K smem) ----
__global__ void __launch_bounds__(256) k_qk()
{
    __shared__ __half QK[2 * 128 * 72];        // Qs | Ks, reused as St staging
    __shared__ float  psumS[128][4];
    __half* Qs = QK;
    __half* Ks = QK + 128 * 72;
    __half* St = QK;                           // 128 x 136 staging

    int pidx = blockIdx.x;       // 0..135 lower-tri pair (ti>=tj)
    int ti = (int)((sqrtf(8.f * pidx + 1.f) - 1.f) * 0.5f);
    while ((ti + 1) * (ti + 2) / 2 <= pidx) ti++;
    while (ti * (ti + 1) / 2 > pidx) ti--;
    int tj = pidx - ti * (ti + 1) / 2;
    int bh = blockIdx.y;

    const __half* qb = g_qh + ((size_t)bh * NN + ti * 128) * DD;
    const __half* kb = g_kh + ((size_t)bh * NN + tj * 128) * DD;

    int tid = threadIdx.x;
#pragma unroll
    for (int p = 0; p < 4; p++) {
        int idx = p * 256 + tid;            // 1024 = 128 rows x 8 chunks
        int r = idx >> 3, c8 = idx & 7;
        *(uint4*)&Qs[r * 72 + c8 * 8] = *(const uint4*)&qb[r * 64 + c8 * 8];
        *(uint4*)&Ks[r * 72 + c8 * 8] = *(const uint4*)&kb[r * 64 + c8 * 8];
    }
    __syncthreads();

    int w = tid >> 5, l = tid & 31;
    int wm0 = (w >> 2) * 64;                // warp rows
    int wn0 = (w & 3) * 32;                 // warp cols
    unsigned qbase = sm_addr(Qs), kbase = sm_addr(Ks);

    float acc[4][4][4];
#pragma unroll
    for (int mi = 0; mi < 4; mi++)
#pragma unroll
        for (int ni = 0; ni < 4; ni++)
#pragma unroll
            for (int u = 0; u < 4; u++) acc[mi][ni][u] = 0.f;

#pragma unroll
    for (int kk = 0; kk < 64; kk += 16) {
        unsigned a[4][4], b[4][2];
#pragma unroll
        for (int mi = 0; mi < 4; mi++)
            ldsm_x4(a[mi], qbase + ((wm0 + mi * 16 + (l & 15)) * 72 + kk + (l >> 4) * 8) * 2);
#pragma unroll
        for (int ni = 0; ni < 4; ni++)
            ldsm_x2(b[ni], kbase + ((wn0 + ni * 8 + (l & 7)) * 72 + kk + ((l >> 3) & 1) * 8) * 2);
#pragma unroll
        for (int mi = 0; mi < 4; mi++)
#pragma unroll
            for (int ni = 0; ni < 4; ni++)
                mma16816(acc[mi][ni], a[mi], b[ni]);
    }
    __syncthreads();               // Qs/Ks dead -> safe to reuse as St

    float kmaxv = g_kmax[bh];
    bool isdiag = (ti == tj);
    int grp = l >> 2, qd = l & 3;

#pragma unroll
    for (int mi = 0; mi < 4; mi++) {
#pragma unroll
        for (int h = 0; h < 2; h++) {
            int row = wm0 + mi * 16 + grp + h * 8;
            float cb = SCALE * g_qnorm[(size_t)bh * NN + ti * 128 + row] * kmaxv;
            float rsum = 0.f;
#pragma unroll
            for (int ni = 0; ni < 4; ni++) {
                int col = wn0 + ni * 8 + qd * 2;
                float e0 = __expf(acc[mi][ni][2 * h]     * SCALE - cb);
                float e1 = __expf(acc[mi][ni][2 * h + 1] * SCALE - cb);
                if (isdiag && col     > row) e0 = 0.f;
                if (isdiag && col + 1 > row) e1 = 0.f;
                rsum += e0 + e1;
                *(unsigned*)&St[row * 136 + col] = h2u(e0, e1);
            }
            rsum += __shfl_xor_sync(0xffffffff, rsum, 1);
            rsum += __shfl_xor_sync(0xffffffff, rsum, 2);
            if (qd == 0) psumS[row][w & 3] = rsum;
        }
    }
    __syncthreads();

    __half* Sb = g_S + (size_t)bh * NN * NN;
#pragma unroll
    for (int p = 0; p < 8; p++) {
        int idx = p * 256 + tid;           // 2048 = 128 rows x 16 chunks
        int r = idx >> 4, c8 = idx & 15;
        *(uint4*)&Sb[(size_t)(ti * 128 + r) * NN + tj * 128 + c8 * 8] =
            *(uint4*)&St[r * 136 + c8 * 8];
    }
    if (tid < 128) {
        float s = psumS[tid][0] + psumS[tid][1] + psumS[tid][2] + psumS[tid][3];
        g_psum[((size_t)bh * NN + ti * 128 + tid) * 16 + tj] = s;
    }
}

// ---------------- K3: reduce partial row sums ----------------
__global__ void k_rsum()
{
    size_t idx = (size_t)blockIdx.x * 256 + threadIdx.x;   // BH*NN rows
    int i = (int)(idx & (NN - 1));
    int nt = (i >> 7) + 1;
    const float* p = g_psum + idx * 16;
    float s = 0.f;
    for (int t = 0; t < nt; t++) s += p[t];
    g_rsum[idx] = s;
}

// ---- K4 (fused): normalize + head-mix + PV, no P intermediate. e-QUARTER CTAs ----
// CTA = (b, 32-row i-band t, e-quarter eq). Warp w owns e = eq*4 + (w>>1), mi = w&1.
// S double-buffered cp.async; V single-buffered, its fetch overlapped with
// normalize+mix. 97.8KB smem -> 2 CTAs/SM (16 warps) for latency hiding.
// S is already causally masked by k_qk, so mixed P is zero above the diagonal.
__global__ void __launch_bounds__(256, 2) k_mixpv(const float* __restrict__ Wpost,
                                                  float* __restrict__ out)
{
    extern __shared__ char smb[];
    float*  invl = (float*)(smb);                         // 16x32 fp32      (2048B)
    __half* Wh   = (__half*)(smb + 2048);                 // 16x24 halves    (pad 1024B)
    __half* BsA[2] = { (__half*)(smb + 3072),             // 16f x 1032 halves (33024B)
                       (__half*)(smb + 36096) };          // 33024B
    __half* Vs   = (__half*)(smb + 69120);                // 4e x 32 x 72 halves (18432B)
    __half* Ps   = (__half*)(smb + 87552);                // 4e x 1280 halves (10240B)
    // total 97792B

    int bi = blockIdx.x;
    int eq = bi & 3;                       // e-quarter; quads adjacent -> S L2 reuse
    int t  = 63 - ((bi >> 2) & 63);        // heavy i-bands first
    int b  = bi >> 8;
    int i0 = t * 32;

    int tid = threadIdx.x;
    int w = tid >> 5, l = tid & 31;
    int grp = l >> 2, qd = l & 3;
    int el = w >> 1;                       // local e 0..3
    int mi = w & 1;                        // i-half 0..1

    // W rows 0..3 = this quarter's e rows; rows 4..15 zero
    {
        int r = tid >> 4, f = tid & 15;
        float wv = (r < 4) ? Wpost[(eq * 4 + r) * HH + f] : 0.f;
        Wh[r * 24 + f] = __float2half_rn(wv);
    }
#pragma unroll
    for (int q2 = 0; q2 < 2; q2++) {
        int idx = q2 * 256 + tid;          // 512 = 16f x 32i
        int f = idx >> 5, r = idx & 31;
        invl[f * 32 + r] = 1.0f / g_rsum[(size_t)(b * HH + f) * NN + i0 + r];
    }
    __syncthreads();

    unsigned wfrag[4];
    ldsm_x4(wfrag, sm_addr(Wh) + ((l & 15) * 24 + (l >> 4) * 8) * 2);

    float acc[8][4];
#pragma unroll
    for (int ni = 0; ni < 8; ni++)
#pragma unroll
        for (int u = 0; u < 4; u++) acc[ni][u] = 0.f;

    auto prefetch_S = [&](int jt, int buf) {
        int j0 = jt * 32;
        __half* Bs = BsA[buf];
#pragma unroll
        for (int p = 0; p < 8; p++) {      // 16f x 32r x 4 chunks
            int idx = p * 256 + tid;
            int f = idx >> 7, r = (idx >> 2) & 31, c = idx & 3;
            cp16(sm_addr(&Bs[f * 1032 + r * 32 + c * 8]),
                 &g_S[((size_t)(b * HH + f) * NN + i0 + r) * NN + j0 + c * 8]);
        }
        cp_commit();
    };
    auto prefetch_V = [&](int jt) {
        int j0 = jt * 32;
#pragma unroll
        for (int p = 0; p < 4; p++) {      // 4e x 32r x 8 chunks
            int idx = p * 256 + tid;
            int e = idx >> 8, r = (idx >> 3) & 31, c8 = idx & 7;
            cp16(sm_addr(&Vs[e * 2304 + r * 72 + c8 * 8]),
                 &g_vh[((size_t)(b * HH + eq * 4 + e) * NN + j0 + r) * DD + c8 * 8]);
        }
        cp_commit();
    };

    int njt = t + 1;
    prefetch_S(0, 0);                      // group: S(0)
    prefetch_V(0);                         // group: V(0)
    for (int jt = 0; jt < njt; jt++) {
        int cur = jt & 1;
        if (jt + 1 < njt) {
            prefetch_S(jt + 1, 1 - cur);   // group: S(jt+1)
            asm volatile("cp.async.wait_group 2;\n");  // S(jt) done; V(jt),S(jt+1) pending
        } else {
            asm volatile("cp.async.wait_group 1;\n");  // S(jt) done; V(jt) pending
        }
        __syncthreads();

        // normalize in place: Sn = S * invl[f][i]   (V(jt) still streaming in)
        {
            __half* Bs = BsA[cur];
#pragma unroll
            for (int q2 = 0; q2 < 16; q2++) {
                int idx = q2 * 256 + tid;  // 4096 uint2
                int f = idx >> 8, i = (idx >> 3) & 31, c4 = idx & 7;
                __half* p = &Bs[f * 1032 + i * 32 + c4 * 4];
                uint2 uv = *(uint2*)p;
                float4 v4 = u2f4(uv);
                float il = invl[f * 32 + i];
                *(uint2*)p = make_uint2(h2u(v4.x * il, v4.y * il),
                                        h2u(v4.z * il, v4.w * il));
            }
        }
        __syncthreads();

        // mix: Ps[e(4), i(32), j(32)] = W(4x16) @ Sn(16f x 1024 sites)
        {
            unsigned bbase = sm_addr(BsA[cur]);
#pragma unroll
            for (int tt = 0; tt < 16; tt++) {
                int s0 = (w * 16 + tt) * 8;
                unsigned bfr[2];
                ldsm_x2t(bfr, bbase + ((l & 15) * 1032 + s0) * 2);
                float c[4] = {0.f, 0.f, 0.f, 0.f};
                mma16816(c, wfrag, bfr);
                if (grp < 4) {
                    int s = s0 + qd * 2;
                    int ii = s >> 5, jj = s & 31;
                    *(unsigned*)&Ps[grp * 1280 + ii * 40 + jj] = h2u(c[0], c[1]);
                }
            }
        }
        // wait for V(jt): pending after it = S(jt+1) if issued
        if (jt + 1 < njt) asm volatile("cp.async.wait_group 1;\n");
        else              asm volatile("cp.async.wait_group 0;\n");
        __syncthreads();

        // PV: acc[e=el] += P_e(16i x 32j slice mi) @ V_e(32j x 64d)
        {
            unsigned pbase = sm_addr(Ps) + el * 1280 * 2;
            unsigned vbase = sm_addr(Vs) + el * 2304 * 2;
#pragma unroll
            for (int kk = 0; kk < 32; kk += 16) {
                unsigned a[4], bfr[8][2];
                ldsm_x4(a, pbase + ((mi * 16 + (l & 15)) * 40 + kk + (l >> 4) * 8) * 2);
#pragma unroll
                for (int ni = 0; ni < 8; ni++)
                    ldsm_x2t(bfr[ni], vbase + ((kk + (l & 15)) * 72 + ni * 8) * 2);
#pragma unroll
                for (int ni = 0; ni < 8; ni++)
                    mma16816(acc[ni], a, bfr[ni]);
            }
        }
        __syncthreads();   // Ps/Bs[cur]/Vs free before reuse
        if (jt + 1 < njt) prefetch_V(jt + 1);   // group: V(jt+1), overlaps next norm+mix
    }

    // epilogue: out[b, eq*4+el, i0 + mi*16 + row, col]
#pragma unroll
    for (int h = 0; h < 2; h++) {
        int row = mi * 16 + grp + h * 8;
#pragma unroll
        for (int ni = 0; ni < 8; ni++) {
            int col = ni * 8 + qd * 2;
            float2 o = make_float2(acc[ni][2 * h], acc[ni][2 * h + 1]);
            *(float2*)&out[((size_t)(b * HH + eq * 4 + el) * NN + i0 + row) * DD + col] = o;
        }
    }
}

// ---------------- launcher ----------------
extern "C" void kernel_launch(void* const* d_in, const int* in_sizes, int n_in,
                              void* d_out, int out_size)
{
    const float* q     = (const float*)d_in[0];
    const float* k     = (const float*)d_in[1];
    const float* v     = (const float*)d_in[2];
    const float* Wpre  = (const float*)d_in[3];
    const float* Wpost = (const float*)d_in[4];
    float* out = (float*)d_out;

    cudaFuncSetAttribute(k_mixpv, cudaFuncAttributeMaxDynamicSharedMemorySize, 97792);

    // 1) fused prep: head-mix q,k + v->fp16 + q-norms + k-max
    k_prep<<<dim3(NN / 16, BB), 256>>>(q, k, v, Wpre);

    // 2) scores via tensor cores + fused exp(s-c) + partial row sums
    k_qk<<<dim3(136, BH), 256>>>();

    // 2b) reduce partial row sums
    k_rsum<<<(BH * NN) / 256, 256>>>();

    // 3) fused normalize + head-mix + PV (no P intermediate), e-quarter CTAs, 2 CTA/SM
    k_mixpv<<<512, 256, 97792>>>(Wpost, out);
}